// round 11
// baseline (speedup 1.0000x reference)
#include <cuda_runtime.h>
#include <cstdint>

#define SEQ     256
#define BATCH   512
#define IN_DIM  256
#define HDIM    8
#define DIN     264          // IN_DIM + HDIM
#define NROWS   (SEQ * BATCH)

// Scratch: pre-activations, bias folded in.
// Layout: zx[(t*BATCH + b)*32 + q*4 + g]  (gate-minor: recur lane does 1 LDG.128)
// Padded one t-row so the recur prefetch never reads OOB.
__device__ __align__(16) float g_zx[(size_t)(NROWS + BATCH) * 32];

// Ready flags: one per gemm tile (64 rows). fidx = t*8 + oct, oct = b>>6.
// [0,2048) real, [2048,2304) pad preset to 1 (t >= SEQ).
#define NFLAG_REAL 2048
#define NFLAG_PAD  2304
__device__ unsigned g_flag[NFLAG_PAD];

typedef unsigned long long ull;

__device__ __forceinline__ void ffma2(ull &d, ull a, ull b) {
    asm("fma.rn.f32x2 %0, %1, %2, %0;" : "+l"(d) : "l"(a), "l"(b));
}
__device__ __forceinline__ ull mul2(ull a, ull b) {
    ull r; asm("mul.rn.f32x2 %0, %1, %2;" : "=l"(r) : "l"(a), "l"(b)); return r;
}
__device__ __forceinline__ ull add2(ull a, ull b) {
    ull r; asm("add.rn.f32x2 %0, %1, %2;" : "=l"(r) : "l"(a), "l"(b)); return r;
}
__device__ __forceinline__ ull pack2(float lo, float hi) {
    ull r; asm("mov.b64 %0, {%1, %2};" : "=l"(r) : "f"(lo), "f"(hi)); return r;
}
__device__ __forceinline__ void unpack2(float &lo, float &hi, ull v) {
    asm("mov.b64 {%0, %1}, %2;" : "=f"(lo), "=f"(hi) : "l"(v));
}
__device__ __forceinline__ float tanh_approx(float x) {
    float y; asm("tanh.approx.f32 %0, %1;" : "=f"(y) : "f"(x)); return y;
}
__device__ __forceinline__ void cpasync16(void* dst, const void* src) {
    unsigned ds = (unsigned)__cvta_generic_to_shared(dst);
    asm volatile("cp.async.cg.shared.global [%0], [%1], 16;" :: "r"(ds), "l"(src));
}
__device__ __forceinline__ void cp_commit() { asm volatile("cp.async.commit_group;"); }
template <int N> __device__ __forceinline__ void cp_wait() {
    asm volatile("cp.async.wait_group %0;" :: "n"(N));
}
__device__ __forceinline__ unsigned ld_acq(const unsigned* p) {
    unsigned v; asm volatile("ld.acquire.gpu.global.b32 %0, [%1];" : "=r"(v) : "l"(p)); return v;
}
__device__ __forceinline__ unsigned ld_rlx(const unsigned* p) {
    unsigned v; asm volatile("ld.relaxed.gpu.global.b32 %0, [%1];" : "=r"(v) : "l"(p)); return v;
}
__device__ __forceinline__ void st_rel(unsigned* p, unsigned v) {
    asm volatile("st.release.gpu.global.b32 [%0], %1;" :: "l"(p), "r"(v));
}
__device__ __forceinline__ void fence_acq() {
    asm volatile("fence.acq_rel.gpu;" ::: "memory");
}
__device__ __forceinline__ void sts_v2(unsigned addr, float a, float b) {
    asm volatile("st.shared.v2.f32 [%0], {%1, %2};" :: "r"(addr), "f"(a), "f"(b));
}
__device__ __forceinline__ ull lds_b64(unsigned addr) {
    ull v; asm volatile("ld.shared.b64 %0, [%1];" : "=l"(v) : "r"(addr)); return v;
}

__global__ void init_flags() {
    int i = blockIdx.x * blockDim.x + threadIdx.x;
    if (i < NFLAG_PAD) g_flag[i] = (i < NFLAG_REAL) ? 0u : 1u;
}

// ---------------------------------------------------------------------------
// Fused kernel. Blocks 0..15: recur (8 warps x 4 elements). Blocks 16..2063:
// gemm tiles of 64 rows, st.release flag on completion.
// ---------------------------------------------------------------------------
#define GEMM_BLOCKS 2048
#define RECUR_BLOCKS 16
#define KCH    32
#define NCHUNK 8

struct RecurEx {
    float4 cv[4][17];   // per elem: slots 0..6 = (1,1,1,1) pad; 7+q = cos vec; 15,16 pad
    ull    hd[32];      // duplicated h: index j*4 + e
};

union SmemU {
    struct { float w_s[32 * 256]; float xs[2][64 * 32]; } g;   // 48KB
    RecurEx ex[8];                                              // ~10.5KB
};

__global__ void __launch_bounds__(256)
qlstm_fused(const float* __restrict__ x,
            const float* __restrict__ Wf, const float* __restrict__ bf,
            const float* __restrict__ Wi, const float* __restrict__ bi,
            const float* __restrict__ Wu, const float* __restrict__ bu,
            const float* __restrict__ Wo, const float* __restrict__ bo,
            const float* __restrict__ pf, const float* __restrict__ pi_,
            const float* __restrict__ pu, const float* __restrict__ po,
            float* __restrict__ out)
{
    __shared__ __align__(16) SmemU sm;

    const int tid  = threadIdx.x;
    const int lane = tid & 31;

    if (blockIdx.x >= RECUR_BLOCKS) {
        // ================= GEMM role: 64 rows = tile gb ====================
        const int gb   = blockIdx.x - RECUR_BLOCKS;
        const int warp = tid >> 5;
        const int row0  = gb * 64;
        const int wrow0 = warp * 8;

        float* w_s = sm.g.w_s;

        #pragma unroll
        for (int i = 0; i < 8; i++) {
            int idx = tid + 256 * i;
            int o = idx >> 6, s = idx & 63;
            int sw = (s & ~7) | ((s & 7) ^ (o & 7));
            int g = o >> 3, q = o & 7;
            const float* base = (g == 0 ? Wf : (g == 1 ? Wi : (g == 2 ? Wu : Wo)));
            cpasync16(&w_s[o * 256 + sw * 4], base + q * DIN + s * 4);
        }

        auto load_x = [&](int kc, int buf) {
            #pragma unroll
            for (int i = 0; i < 2; i++) {
                int idx = tid + 256 * i;          // 512 slots: 64 rows x 8 slots
                int r = idx >> 3, s = idx & 7;
                cpasync16(&sm.g.xs[buf][r * 32 + s * 4],
                          x + (size_t)(row0 + r) * IN_DIM + kc * KCH + s * 4);
            }
        };

        load_x(0, 0); cp_commit();                // group: {W, x0}

        ull acc[8];
        #pragma unroll
        for (int r = 0; r < 8; r++) acc[r] = 0ULL;

        #pragma unroll 1
        for (int kc = 0; kc < NCHUNK; kc++) {
            if (kc < NCHUNK - 1) { load_x(kc + 1, (kc + 1) & 1); cp_commit(); }
            if (kc < NCHUNK - 1) cp_wait<1>(); else cp_wait<0>();
            __syncthreads();

            ull wreg[16];
            #pragma unroll
            for (int j = 0; j < 8; j++) {
                int s  = kc * 8 + j;
                int sw = (s & ~7) | ((s & 7) ^ (lane & 7));
                ulonglong2 wv = *reinterpret_cast<const ulonglong2*>(&w_s[lane * 256 + sw * 4]);
                wreg[2 * j] = wv.x; wreg[2 * j + 1] = wv.y;
            }

            const float* xb = sm.g.xs[kc & 1];
            #pragma unroll
            for (int r = 0; r < 8; r++) {
                const ulonglong2* xp = reinterpret_cast<const ulonglong2*>(xb + (wrow0 + r) * 32);
                #pragma unroll
                for (int j = 0; j < 8; j++) {
                    ulonglong2 xv = xp[j];         // full-warp broadcast LDS.128
                    ffma2(acc[r], xv.x, wreg[2 * j]);
                    ffma2(acc[r], xv.y, wreg[2 * j + 1]);
                }
            }
            __syncthreads();
        }

        const int g = lane >> 3, q = lane & 7;    // this lane's output o = g*8+q
        const float bias = (g == 0 ? bf : (g == 1 ? bi : (g == 2 ? bu : bo)))[q];

        #pragma unroll
        for (int r = 0; r < 8; r++) {
            float2 p = *reinterpret_cast<float2*>(&acc[r]);
            g_zx[(size_t)(row0 + wrow0 + r) * 32 + q * 4 + g] = p.x + p.y + bias;
        }

        __syncthreads();
        if (tid == 0) st_rel(&g_flag[gb], 1u);     // fidx == gb == t*8 + oct
    } else {
        // ========== RECUR role: lane = (elem, qubit), 4 elems/warp =========
        const int wid = tid >> 5;
        const int e   = lane >> 3, q = lane & 7;
        const int b   = blockIdx.x * 32 + wid * 4 + e;
        const int oct = blockIdx.x >> 1;           // uniform across block

        RecurEx& ex = sm.ex[wid];

        // recurrent weights for this qubit, packed (f,i) and (u,o)
        ull wfi[8], wuo[8];
        #pragma unroll
        for (int j = 0; j < 8; j++) {
            wfi[j] = pack2(Wf[q * DIN + IN_DIM + j], Wi[q * DIN + IN_DIM + j]);
            wuo[j] = pack2(Wu[q * DIN + IN_DIM + j], Wo[q * DIN + IN_DIM + j]);
        }
        float cthf = __cosf(pf[q]), cthi = __cosf(pi_[q]);
        float cthu = __cosf(pu[q]), ctho = __cosf(po[q]);
        if (q == 0) { cthf *= 0.5f; cthi *= 0.5f; ctho *= 0.5f; }  // sigmoid 0.5x fold

        // Prologue: pad slots = (1,1,1,1); h dup = 0.
        if (q < 7) ex.cv[e][q] = make_float4(1.f, 1.f, 1.f, 1.f);
        ex.hd[q * 4 + e] = 0ULL;

        // Precompute smem addresses
        unsigned hd_base = (unsigned)__cvta_generic_to_shared(&ex.hd[0]);
        unsigned hd_st   = hd_base + (q * 4 + e) * 8;     // my dup-h slot
        unsigned hd_ld[8];
        #pragma unroll
        for (int j = 0; j < 8; j++) hd_ld[j] = hd_base + (j * 4 + e) * 8;
        float4* cv_st = &ex.cv[e][7 + q];
        const ulonglong2* cv_win = reinterpret_cast<const ulonglong2*>(&ex.cv[e][q]);

        __syncwarp();

        const float* zp = g_zx + (size_t)b * 32 + q * 4;
        const size_t zstr = (size_t)BATCH * 32;

        float* hx_out = out + (size_t)SEQ * BATCH * HDIM;
        float* cx_out = hx_out + (size_t)BATCH * HDIM;

        float c = 0.f, hnew = 0.f;

        // Windowed flag protocol (flags for t = w8+1..w8+8, loaded 1 window early)
        unsigned fv[8];
        auto load_flags = [&](int w8) {
            #pragma unroll
            for (int i = 0; i < 8; i++)
                fv[i] = ld_rlx(&g_flag[(w8 + 1 + i) * 8 + oct]);
        };

        {   // t=0 tile (blocking acquire)
            unsigned r = ld_acq(&g_flag[oct]);
            while (r == 0) { __nanosleep(128); r = ld_acq(&g_flag[oct]); }
        }
        load_flags(0);
        ulonglong2 z2 = *reinterpret_cast<const ulonglong2*>(zp);

        #pragma unroll 1
        for (int w = 0; w < SEQ / 8; w++) {
            const int tw = w * 8;

            unsigned allv = fv[0] & fv[1] & fv[2] & fv[3] & fv[4] & fv[5] & fv[6] & fv[7];
            if (allv == 0) {
                #pragma unroll
                for (int i = 0; i < 8; i++) {
                    while (fv[i] == 0) {
                        __nanosleep(128);
                        fv[i] = ld_rlx(&g_flag[(tw + 1 + i) * 8 + oct]);
                    }
                }
            }
            fence_acq();
            if (w < SEQ / 8 - 1) load_flags(tw + 8);

            #pragma unroll
            for (int s = 0; s < 8; s++) {
                const int t = tw + s;
                ulonglong2 zn = *reinterpret_cast<const ulonglong2*>(
                    zp + (size_t)(t + 1) * zstr);

                // dot: h read straight from dup-slots (no pack MOVs);
                // two 4-deep ffma2 chains per gate pair, joined by add2.
                ull h0 = lds_b64(hd_ld[0]), h1 = lds_b64(hd_ld[1]);
                ull h2 = lds_b64(hd_ld[2]), h3 = lds_b64(hd_ld[3]);
                ull h4 = lds_b64(hd_ld[4]), h5 = lds_b64(hd_ld[5]);
                ull h6 = lds_b64(hd_ld[6]), h7 = lds_b64(hd_ld[7]);

                ull zfiA = z2.x, zuoA = z2.y;
                ffma2(zfiA, h0, wfi[0]); ffma2(zfiA, h1, wfi[1]);
                ffma2(zfiA, h2, wfi[2]); ffma2(zfiA, h3, wfi[3]);
                ffma2(zuoA, h0, wuo[0]); ffma2(zuoA, h1, wuo[1]);
                ffma2(zuoA, h2, wuo[2]); ffma2(zuoA, h3, wuo[3]);
                ull zfiB = mul2(h4, wfi[4]), zuoB = mul2(h4, wuo[4]);
                ffma2(zfiB, h5, wfi[5]); ffma2(zfiB, h6, wfi[6]); ffma2(zfiB, h7, wfi[7]);
                ffma2(zuoB, h5, wuo[5]); ffma2(zuoB, h6, wuo[6]); ffma2(zuoB, h7, wuo[7]);
                ull zfi = add2(zfiA, zfiB), zuo = add2(zuoA, zuoB);

                float zf, zi, zu, zo;
                unpack2(zf, zi, zfi); unpack2(zu, zo, zuo);

                float cf = __cosf(zf) * cthf;
                float ci = __cosf(zi) * cthi;
                float cu = __cosf(zu) * cthu;
                float co = __cosf(zo) * ctho;

                // publish cos vec; prefix = product of 8 consecutive window
                // slots (pad slots are 1.0) -> no selects, no masks.
                *cv_st = make_float4(cf, ci, cu, co);
                __syncwarp();

                ulonglong2 w0 = cv_win[0], w1 = cv_win[1], w2 = cv_win[2], w3 = cv_win[3];
                ulonglong2 w4 = cv_win[4], w5 = cv_win[5], w6 = cv_win[6], w7 = cv_win[7];
                ull pfi = mul2(mul2(mul2(w0.x, w1.x), mul2(w2.x, w3.x)),
                               mul2(mul2(w4.x, w5.x), mul2(w6.x, w7.x)));
                ull puo = mul2(mul2(mul2(w0.y, w1.y), mul2(w2.y, w3.y)),
                               mul2(mul2(w4.y, w5.y), mul2(w6.y, w7.y)));
                float Pf, Pi, Pu, Po;
                unpack2(Pf, Pi, pfi); unpack2(Pu, Po, puo);

                // activations (local): sigma = 0.5*tanh(P/2)+0.5, fold done
                float af = fmaf(0.5f, tanh_approx(Pf), 0.5f);
                float ai = fmaf(0.5f, tanh_approx(Pi), 0.5f);
                float tu = tanh_approx(Pu);
                float ao = fmaf(0.5f, tanh_approx(Po), 0.5f);

                c    = fmaf(af, c, ai * tu);
                hnew = ao * tanh_approx(c);

                // publish duplicated h (feeds next step's ffma2 directly)
                sts_v2(hd_st, hnew, hnew);
                __syncwarp();

                out[(size_t)t * (BATCH * HDIM) + (size_t)b * HDIM + q] = hnew;
                z2 = zn;
            }
        }

        hx_out[(size_t)b * HDIM + q] = hnew;
        cx_out[(size_t)b * HDIM + q] = c;
    }
}

extern "C" void kernel_launch(void* const* d_in, const int* in_sizes, int n_in,
                              void* d_out, int out_size) {
    const float* inputs = (const float*)d_in[0];
    const float* Wf = (const float*)d_in[1];  const float* bf = (const float*)d_in[2];
    const float* Wi = (const float*)d_in[3];  const float* bi = (const float*)d_in[4];
    const float* Wu = (const float*)d_in[5];  const float* bu = (const float*)d_in[6];
    const float* Wo = (const float*)d_in[7];  const float* bo = (const float*)d_in[8];
    const float* pf  = (const float*)d_in[9];
    const float* pi_ = (const float*)d_in[10];
    const float* pu  = (const float*)d_in[11];
    const float* po  = (const float*)d_in[12];
    float* out = (float*)d_out;

    init_flags<<<9, 256>>>();
    qlstm_fused<<<RECUR_BLOCKS + GEMM_BLOCKS, 256>>>(
        inputs, Wf, bf, Wi, bi, Wu, bu, Wo, bo, pf, pi_, pu, po, out);
}

// round 12
// speedup vs baseline: 1.1147x; 1.1147x over previous
#include <cuda_runtime.h>
#include <cstdint>

#define SEQ     256
#define BATCH   512
#define IN_DIM  256
#define HDIM    8
#define DIN     264          // IN_DIM + HDIM
#define NROWS   (SEQ * BATCH)

// Scratch: pre-activations, bias folded in.
// Layout: zx[(t*BATCH + b)*32 + (g*8 + q)]  (column = lane in both roles)
// Padded one t-row so the recur prefetch never reads OOB.
__device__ __align__(16) float g_zx[(size_t)(NROWS + BATCH) * 32];

// Ready flags: one per gemm tile (64 rows). fidx = t*8 + oct, oct = b>>6.
// [0,2048) real, [2048,2304) pad preset to 1 (t >= SEQ).
#define NFLAG_REAL 2048
#define NFLAG_PAD  2304
__device__ unsigned g_flag[NFLAG_PAD];

typedef unsigned long long ull;

__device__ __forceinline__ void ffma2(ull &d, ull a, ull b) {
    asm("fma.rn.f32x2 %0, %1, %2, %0;" : "+l"(d) : "l"(a), "l"(b));
}
__device__ __forceinline__ float tanh_approx(float x) {
    float y; asm("tanh.approx.f32 %0, %1;" : "=f"(y) : "f"(x)); return y;
}
__device__ __forceinline__ void cpasync16(void* dst, const void* src) {
    unsigned ds = (unsigned)__cvta_generic_to_shared(dst);
    asm volatile("cp.async.cg.shared.global [%0], [%1], 16;" :: "r"(ds), "l"(src));
}
__device__ __forceinline__ void cp_commit() { asm volatile("cp.async.commit_group;"); }
template <int N> __device__ __forceinline__ void cp_wait() {
    asm volatile("cp.async.wait_group %0;" :: "n"(N));
}
__device__ __forceinline__ unsigned ld_acq(const unsigned* p) {
    unsigned v; asm volatile("ld.acquire.gpu.global.b32 %0, [%1];" : "=r"(v) : "l"(p)); return v;
}
__device__ __forceinline__ unsigned ld_rlx(const unsigned* p) {
    unsigned v; asm volatile("ld.relaxed.gpu.global.b32 %0, [%1];" : "=r"(v) : "l"(p)); return v;
}
__device__ __forceinline__ void st_rel(unsigned* p, unsigned v) {
    asm volatile("st.release.gpu.global.b32 [%0], %1;" :: "l"(p), "r"(v));
}
__device__ __forceinline__ void fence_acq() {
    asm volatile("fence.acq_rel.gpu;" ::: "memory");
}

__global__ void init_flags() {
    int i = blockIdx.x * blockDim.x + threadIdx.x;
    if (i < NFLAG_PAD) g_flag[i] = (i < NFLAG_REAL) ? 0u : 1u;
}

// ---------------------------------------------------------------------------
// Fused kernel. Blocks 0..63: recur (8 warps = 8 batch elems each, scalar
// (g,q) layout, TWO smem exchanges per step, window-batched output stores).
// Blocks 64..2111: gemm tiles of 64 rows, st.release flag on completion.
// ---------------------------------------------------------------------------
#define GEMM_BLOCKS 2048
#define RECUR_BLOCKS 64
#define KCH    32
#define NCHUNK 8

union SmemU {
    struct { float w_s[32 * 256]; float xs[2][64 * 32]; } g;   // 48KB
    float ex[8][80];    // per warp: cv[32], a[32], pad
};

__global__ void __launch_bounds__(256)
qlstm_fused(const float* __restrict__ x,
            const float* __restrict__ Wf, const float* __restrict__ bf,
            const float* __restrict__ Wi, const float* __restrict__ bi,
            const float* __restrict__ Wu, const float* __restrict__ bu,
            const float* __restrict__ Wo, const float* __restrict__ bo,
            const float* __restrict__ pf, const float* __restrict__ pi_,
            const float* __restrict__ pu, const float* __restrict__ po,
            float* __restrict__ out)
{
    __shared__ __align__(16) SmemU sm;

    const int tid  = threadIdx.x;
    const int lane = tid & 31;

    if (blockIdx.x >= RECUR_BLOCKS) {
        // ================= GEMM role: 64 rows = tile gb ====================
        const int gb   = blockIdx.x - RECUR_BLOCKS;
        const int warp = tid >> 5;
        const int row0  = gb * 64;
        const int wrow0 = warp * 8;

        float* w_s = sm.g.w_s;

        #pragma unroll
        for (int i = 0; i < 8; i++) {
            int idx = tid + 256 * i;
            int o = idx >> 6, s = idx & 63;
            int sw = (s & ~7) | ((s & 7) ^ (o & 7));
            int g = o >> 3, q = o & 7;
            const float* base = (g == 0 ? Wf : (g == 1 ? Wi : (g == 2 ? Wu : Wo)));
            cpasync16(&w_s[o * 256 + sw * 4], base + q * DIN + s * 4);
        }

        auto load_x = [&](int kc, int buf) {
            #pragma unroll
            for (int i = 0; i < 2; i++) {
                int idx = tid + 256 * i;          // 512 slots: 64 rows x 8 slots
                int r = idx >> 3, s = idx & 7;
                cpasync16(&sm.g.xs[buf][r * 32 + s * 4],
                          x + (size_t)(row0 + r) * IN_DIM + kc * KCH + s * 4);
            }
        };

        load_x(0, 0); cp_commit();                // group: {W, x0}

        ull acc[8];
        #pragma unroll
        for (int r = 0; r < 8; r++) acc[r] = 0ULL;

        #pragma unroll 1
        for (int kc = 0; kc < NCHUNK; kc++) {
            if (kc < NCHUNK - 1) { load_x(kc + 1, (kc + 1) & 1); cp_commit(); }
            if (kc < NCHUNK - 1) cp_wait<1>(); else cp_wait<0>();
            __syncthreads();

            ull wreg[16];
            #pragma unroll
            for (int j = 0; j < 8; j++) {
                int s  = kc * 8 + j;
                int sw = (s & ~7) | ((s & 7) ^ (lane & 7));
                ulonglong2 wv = *reinterpret_cast<const ulonglong2*>(&w_s[lane * 256 + sw * 4]);
                wreg[2 * j] = wv.x; wreg[2 * j + 1] = wv.y;
            }

            const float* xb = sm.g.xs[kc & 1];
            #pragma unroll
            for (int r = 0; r < 8; r++) {
                const ulonglong2* xp = reinterpret_cast<const ulonglong2*>(xb + (wrow0 + r) * 32);
                #pragma unroll
                for (int j = 0; j < 8; j++) {
                    ulonglong2 xv = xp[j];         // full-warp broadcast LDS.128
                    ffma2(acc[r], xv.x, wreg[2 * j]);
                    ffma2(acc[r], xv.y, wreg[2 * j + 1]);
                }
            }
            __syncthreads();
        }

        const int g = lane >> 3, q = lane & 7;    // lane's output o = g*8+q
        const float bias = (g == 0 ? bf : (g == 1 ? bi : (g == 2 ? bu : bo)))[q];

        #pragma unroll
        for (int r = 0; r < 8; r++) {
            float2 p = *reinterpret_cast<float2*>(&acc[r]);
            g_zx[(size_t)(row0 + wrow0 + r) * 32 + lane] = p.x + p.y + bias;
        }

        __syncthreads();
        if (tid == 0) st_rel(&g_flag[gb], 1u);     // fidx == gb == t*8 + oct
    } else {
        // ================= RECUR role: 8 chains per block ==================
        const int wid = tid >> 5;
        const int b   = blockIdx.x * 8 + wid;
        const int oct = blockIdx.x >> 3;           // == b>>6, uniform per block
        const int g = lane >> 3, q = lane & 7;

        float* cvrow = &sm.ex[wid][0];
        float* arow  = &sm.ex[wid][32];

        const float* W = (g == 0 ? Wf : (g == 1 ? Wi : (g == 2 ? Wu : Wo))) + q * DIN + IN_DIM;
        const float* p = (g == 0 ? pf : (g == 1 ? pi_ : (g == 2 ? pu : po)));

        float Whr[8];
        #pragma unroll
        for (int j = 0; j < 8; j++) Whr[j] = W[j];

        float cth = __cosf(p[q]);
        if (g != 2 && q == 0) cth *= 0.5f;         // sigmoid 0.5x folded into prefix
        const float s2 = (g == 2) ? 1.f : 0.5f;
        const float s3 = (g == 2) ? 0.f : 0.5f;

        const bool p1 = (q >= 1), p2 = (q >= 2), p3 = (q >= 3),
                   p4 = (q >= 4), p5 = (q >= 5), p6 = (q >= 6), p7 = (q >= 7);

        const float* zp = g_zx + (size_t)b * 32 + lane;
        const size_t zstr = (size_t)BATCH * 32;

        float* hx_out = out + (size_t)SEQ * BATCH * HDIM;
        float* cx_out = hx_out + (size_t)BATCH * HDIM;

        // full h and c state replicated in every lane (scalar registers)
        float h[8], cst[8];
        #pragma unroll
        for (int j = 0; j < 8; j++) { h[j] = 0.f; cst[j] = 0.f; }
        float hq = 0.f;                            // this lane's h[q], tracked

        // Windowed flag protocol (flags for t = w8+1..w8+8, loaded 1 window early)
        unsigned fv[8];
        auto load_flags = [&](int w8) {
            #pragma unroll
            for (int i = 0; i < 8; i++)
                fv[i] = ld_rlx(&g_flag[(w8 + 1 + i) * 8 + oct]);
        };

        {   // t=0 tile (blocking acquire)
            unsigned r = ld_acq(&g_flag[oct]);
            while (r == 0) { __nanosleep(128); r = ld_acq(&g_flag[oct]); }
        }
        load_flags(0);
        float zcur = zp[0];

        #pragma unroll 1
        for (int w = 0; w < SEQ / 8; w++) {
            const int tw = w * 8;

            unsigned allv = fv[0] & fv[1] & fv[2] & fv[3] & fv[4] & fv[5] & fv[6] & fv[7];
            if (allv == 0) {
                #pragma unroll
                for (int i = 0; i < 8; i++) {
                    while (fv[i] == 0) {
                        __nanosleep(128);
                        fv[i] = ld_rlx(&g_flag[(tw + 1 + i) * 8 + oct]);
                    }
                }
            }
            fence_acq();
            if (w < SEQ / 8 - 1) load_flags(tw + 8);

            float hs[8];                           // window-buffered outputs

            #pragma unroll
            for (int s = 0; s < 8; s++) {
                const int t = tw + s;
                float zn = zp[(size_t)(t + 1) * zstr];

                // recurrent dot, tree-shaped (all-scalar, h in registers)
                float s01 = fmaf(h[1], Whr[1], h[0] * Whr[0]);
                float s23 = fmaf(h[3], Whr[3], h[2] * Whr[2]);
                float s45 = fmaf(h[5], Whr[5], h[4] * Whr[4]);
                float s67 = fmaf(h[7], Whr[7], h[6] * Whr[6]);
                float z = zcur + ((s01 + s23) + (s45 + s67));

                float cv = __cosf(z) * cth;

                // exchange 1: share cos values within gate group
                cvrow[lane] = cv;
                __syncwarp();
                float4 va = *reinterpret_cast<const float4*>(cvrow + g * 8);
                float4 vb = *reinterpret_cast<const float4*>(cvrow + g * 8 + 4);

                float u1 = p1 ? va.y : 1.f, u2 = p2 ? va.z : 1.f, u3 = p3 ? va.w : 1.f;
                float u4 = p4 ? vb.x : 1.f, u5 = p5 ? vb.y : 1.f, u6 = p6 ? vb.z : 1.f;
                float u7 = p7 ? vb.w : 1.f;
                float pr = ((va.x * u1) * (u2 * u3)) * ((u4 * u5) * (u6 * u7));

                float th = tanh_approx(pr);
                float a  = fmaf(s2, th, s3);

                // exchange 2: publish activation; then EVERY lane rebuilds the
                // full (f,i,u,o) table and updates ALL 8 c_j/h_j locally.
                arow[q * 4 + g] = a;
                __syncwarp();
                #pragma unroll
                for (int j = 0; j < 8; j++) {
                    float4 fiuo = *reinterpret_cast<const float4*>(arow + j * 4);
                    cst[j] = fmaf(fiuo.x, cst[j], fiuo.y * fiuo.z);
                    h[j]   = fiuo.w * tanh_approx(cst[j]);
                    if (j == q) hq = h[j];         // FSEL, avoids dynamic index
                }

                hs[s] = hq;
                zcur  = zn;
            }

            // batched, off-critical-path output stores (4x same-addr dup ok)
            #pragma unroll
            for (int s = 0; s < 8; s++)
                out[(size_t)(tw + s) * (BATCH * HDIM) + (size_t)b * HDIM + q] = hs[s];
        }

        // epilogue: extract c_q once
        float cq = 0.f;
        #pragma unroll
        for (int j = 0; j < 8; j++) if (j == q) cq = cst[j];

        hx_out[(size_t)b * HDIM + q] = hq;
        cx_out[(size_t)b * HDIM + q] = cq;
    }
}

extern "C" void kernel_launch(void* const* d_in, const int* in_sizes, int n_in,
                              void* d_out, int out_size) {
    const float* inputs = (const float*)d_in[0];
    const float* Wf = (const float*)d_in[1];  const float* bf = (const float*)d_in[2];
    const float* Wi = (const float*)d_in[3];  const float* bi = (const float*)d_in[4];
    const float* Wu = (const float*)d_in[5];  const float* bu = (const float*)d_in[6];
    const float* Wo = (const float*)d_in[7];  const float* bo = (const float*)d_in[8];
    const float* pf  = (const float*)d_in[9];
    const float* pi_ = (const float*)d_in[10];
    const float* pu  = (const float*)d_in[11];
    const float* po  = (const float*)d_in[12];
    float* out = (float*)d_out;

    init_flags<<<9, 256>>>();
    qlstm_fused<<<RECUR_BLOCKS + GEMM_BLOCKS, 256>>>(
        inputs, Wf, bf, Wi, bi, Wu, bu, Wo, bo, pf, pi_, pu, po, out);
}

// round 13
// speedup vs baseline: 1.3656x; 1.2251x over previous
#include <cuda_runtime.h>
#include <cstdint>

#define SEQ     256
#define BATCH   512
#define IN_DIM  256
#define HDIM    8
#define DIN     264          // IN_DIM + HDIM
#define NROWS   (SEQ * BATCH)

// Scratch: pre-activations, bias folded in.
// Layout: zx[(t*BATCH + b)*32 + (g*8 + q)]  (column = lane in both roles)
// Padded one t-row so the recur prefetch never reads OOB.
__device__ __align__(16) float g_zx[(size_t)(NROWS + BATCH) * 32];

// Ready flags: one per gemm tile (64 rows). fidx = t*8 + oct, oct = b>>6.
// [0,2048) real, [2048,2304) pad preset to 1 (t >= SEQ).
#define NFLAG_REAL 2048
#define NFLAG_PAD  2304
__device__ unsigned g_flag[NFLAG_PAD];

typedef unsigned long long ull;

__device__ __forceinline__ void ffma2(ull &d, ull a, ull b) {
    asm("fma.rn.f32x2 %0, %1, %2, %0;" : "+l"(d) : "l"(a), "l"(b));
}
__device__ __forceinline__ float tanh_approx(float x) {
    float y; asm("tanh.approx.f32 %0, %1;" : "=f"(y) : "f"(x)); return y;
}
__device__ __forceinline__ void cpasync16(void* dst, const void* src) {
    unsigned ds = (unsigned)__cvta_generic_to_shared(dst);
    asm volatile("cp.async.cg.shared.global [%0], [%1], 16;" :: "r"(ds), "l"(src));
}
__device__ __forceinline__ void cp_commit() { asm volatile("cp.async.commit_group;"); }
template <int N> __device__ __forceinline__ void cp_wait() {
    asm volatile("cp.async.wait_group %0;" :: "n"(N));
}
__device__ __forceinline__ unsigned ld_acq(const unsigned* p) {
    unsigned v; asm volatile("ld.acquire.gpu.global.b32 %0, [%1];" : "=r"(v) : "l"(p)); return v;
}
__device__ __forceinline__ unsigned ld_rlx(const unsigned* p) {
    unsigned v; asm volatile("ld.relaxed.gpu.global.b32 %0, [%1];" : "=r"(v) : "l"(p)); return v;
}
__device__ __forceinline__ void st_rel(unsigned* p, unsigned v) {
    asm volatile("st.release.gpu.global.b32 [%0], %1;" :: "l"(p), "r"(v));
}
__device__ __forceinline__ void fence_acq() {
    asm volatile("fence.acq_rel.gpu;" ::: "memory");
}

// Sync-free warp-convergent smem exchange primitives. asm volatile keeps
// STS->LDS program order; a convergent warp issues per-warp in program
// order, so the LDS instruction sees all lanes' STS data. NO WARPSYNC.
__device__ __forceinline__ void sts_x(unsigned a, float v) {
    asm volatile("st.volatile.shared.f32 [%0], %1;" :: "r"(a), "f"(v));
}
__device__ __forceinline__ float4 lds128_x(unsigned a) {
    float4 r;
    asm volatile("ld.volatile.shared.v4.f32 {%0,%1,%2,%3}, [%4];"
                 : "=f"(r.x), "=f"(r.y), "=f"(r.z), "=f"(r.w) : "r"(a));
    return r;
}

__global__ void init_flags() {
    int i = blockIdx.x * blockDim.x + threadIdx.x;
    if (i < NFLAG_PAD) g_flag[i] = (i < NFLAG_REAL) ? 0u : 1u;
}

// ---------------------------------------------------------------------------
// Fused kernel. Blocks 0..63: recur (8 warps = 8 batch elems each, scalar
// (g,q) layout, 3 sync-free smem exchanges per step, 16-step flag windows,
// window-batched stores). Blocks 64..2111: gemm tiles of 64 rows.
// ---------------------------------------------------------------------------
#define GEMM_BLOCKS 2048
#define RECUR_BLOCKS 64
#define KCH    32
#define NCHUNK 8
#define WIN    16

union SmemU {
    struct { float w_s[32 * 256]; float xs[2][64 * 32]; } g;   // 48KB
    float ex[8][80];    // per warp: cv[32], a[32], h[8], pad
};

__global__ void __launch_bounds__(256)
qlstm_fused(const float* __restrict__ x,
            const float* __restrict__ Wf, const float* __restrict__ bf,
            const float* __restrict__ Wi, const float* __restrict__ bi,
            const float* __restrict__ Wu, const float* __restrict__ bu,
            const float* __restrict__ Wo, const float* __restrict__ bo,
            const float* __restrict__ pf, const float* __restrict__ pi_,
            const float* __restrict__ pu, const float* __restrict__ po,
            float* __restrict__ out)
{
    __shared__ __align__(16) SmemU sm;

    const int tid  = threadIdx.x;
    const int lane = tid & 31;

    if (blockIdx.x >= RECUR_BLOCKS) {
        // ================= GEMM role: 64 rows = tile gb ====================
        const int gb   = blockIdx.x - RECUR_BLOCKS;
        const int warp = tid >> 5;
        const int row0  = gb * 64;
        const int wrow0 = warp * 8;

        float* w_s = sm.g.w_s;

        #pragma unroll
        for (int i = 0; i < 8; i++) {
            int idx = tid + 256 * i;
            int o = idx >> 6, s = idx & 63;
            int sw = (s & ~7) | ((s & 7) ^ (o & 7));
            int g = o >> 3, q = o & 7;
            const float* base = (g == 0 ? Wf : (g == 1 ? Wi : (g == 2 ? Wu : Wo)));
            cpasync16(&w_s[o * 256 + sw * 4], base + q * DIN + s * 4);
        }

        auto load_x = [&](int kc, int buf) {
            #pragma unroll
            for (int i = 0; i < 2; i++) {
                int idx = tid + 256 * i;          // 512 slots: 64 rows x 8 slots
                int r = idx >> 3, s = idx & 7;
                cpasync16(&sm.g.xs[buf][r * 32 + s * 4],
                          x + (size_t)(row0 + r) * IN_DIM + kc * KCH + s * 4);
            }
        };

        load_x(0, 0); cp_commit();                // group: {W, x0}

        ull acc[8];
        #pragma unroll
        for (int r = 0; r < 8; r++) acc[r] = 0ULL;

        #pragma unroll 1
        for (int kc = 0; kc < NCHUNK; kc++) {
            if (kc < NCHUNK - 1) { load_x(kc + 1, (kc + 1) & 1); cp_commit(); }
            if (kc < NCHUNK - 1) cp_wait<1>(); else cp_wait<0>();
            __syncthreads();

            ull wreg[16];
            #pragma unroll
            for (int j = 0; j < 8; j++) {
                int s  = kc * 8 + j;
                int sw = (s & ~7) | ((s & 7) ^ (lane & 7));
                ulonglong2 wv = *reinterpret_cast<const ulonglong2*>(&w_s[lane * 256 + sw * 4]);
                wreg[2 * j] = wv.x; wreg[2 * j + 1] = wv.y;
            }

            const float* xb = sm.g.xs[kc & 1];
            #pragma unroll
            for (int r = 0; r < 8; r++) {
                const ulonglong2* xp = reinterpret_cast<const ulonglong2*>(xb + (wrow0 + r) * 32);
                #pragma unroll
                for (int j = 0; j < 8; j++) {
                    ulonglong2 xv = xp[j];         // full-warp broadcast LDS.128
                    ffma2(acc[r], xv.x, wreg[2 * j]);
                    ffma2(acc[r], xv.y, wreg[2 * j + 1]);
                }
            }
            __syncthreads();
        }

        const int g = lane >> 3, q = lane & 7;
        const float bias = (g == 0 ? bf : (g == 1 ? bi : (g == 2 ? bu : bo)))[q];

        #pragma unroll
        for (int r = 0; r < 8; r++) {
            float2 p = *reinterpret_cast<float2*>(&acc[r]);
            g_zx[(size_t)(row0 + wrow0 + r) * 32 + lane] = p.x + p.y + bias;
        }

        __syncthreads();
        if (tid == 0) st_rel(&g_flag[gb], 1u);     // fidx == gb == t*8 + oct
    } else {
        // ================= RECUR role: 8 chains per block ==================
        const int wid = tid >> 5;
        const int b   = blockIdx.x * 8 + wid;
        const int oct = blockIdx.x >> 3;           // == b>>6, uniform per block
        const int g = lane >> 3, q = lane & 7;

        // shared-address registers for the sync-free exchanges
        float* exw = &sm.ex[wid][0];
        const unsigned cvb = (unsigned)__cvta_generic_to_shared(exw);
        const unsigned ab  = cvb + 32 * 4;
        const unsigned hbm = cvb + 64 * 4;
        const unsigned st1 = cvb + lane * 4;
        const unsigned rd1a = cvb + g * 32, rd1b = rd1a + 16;
        const unsigned st2 = ab + (q * 4 + g) * 4;
        const unsigned rd2 = ab + q * 16;
        const unsigned st3 = hbm + q * 4;          // 4 lanes dup same value: ok
        const unsigned rd3a = hbm, rd3b = hbm + 16;

        const float* W = (g == 0 ? Wf : (g == 1 ? Wi : (g == 2 ? Wu : Wo))) + q * DIN + IN_DIM;
        const float* p = (g == 0 ? pf : (g == 1 ? pi_ : (g == 2 ? pu : po)));

        float Whr[8];
        #pragma unroll
        for (int j = 0; j < 8; j++) Whr[j] = W[j];

        float cth = __cosf(p[q]);
        if (g != 2 && q == 0) cth *= 0.5f;         // sigmoid 0.5x folded into prefix
        const float s2 = (g == 2) ? 1.f : 0.5f;
        const float s3 = (g == 2) ? 0.f : 0.5f;

        const bool p1 = (q >= 1), p2 = (q >= 2), p3 = (q >= 3),
                   p4 = (q >= 4), p5 = (q >= 5), p6 = (q >= 6), p7 = (q >= 7);

        const float* zp = g_zx + (size_t)b * 32 + lane;
        const size_t zstr = (size_t)BATCH * 32;

        float* hx_out = out + (size_t)SEQ * BATCH * HDIM;
        float* cx_out = hx_out + (size_t)BATCH * HDIM;

        float h[8];
        #pragma unroll
        for (int j = 0; j < 8; j++) h[j] = 0.f;
        float c = 0.f, hnew = 0.f;

        // 16-step flag windows, loaded one window early (latency hidden).
        unsigned fv[WIN];
        auto load_flags = [&](int w16) {           // flags for t = w16+1..w16+16
            #pragma unroll
            for (int i = 0; i < WIN; i++)
                fv[i] = ld_rlx(&g_flag[(w16 + 1 + i) * 8 + oct]);
        };

        {   // t=0 tile (blocking acquire)
            unsigned r = ld_acq(&g_flag[oct]);
            while (r == 0) { __nanosleep(128); r = ld_acq(&g_flag[oct]); }
        }
        load_flags(0);
        float zcur = zp[0];

        #pragma unroll 1
        for (int w = 0; w < SEQ / WIN; w++) {
            const int tw = w * WIN;

            unsigned allv = fv[0];
            #pragma unroll
            for (int i = 1; i < WIN; i++) allv &= fv[i];
            if (allv == 0) {                        // warp-uniform branch
                #pragma unroll
                for (int i = 0; i < WIN; i++) {
                    while (fv[i] == 0) {
                        __nanosleep(128);
                        fv[i] = ld_rlx(&g_flag[(tw + 1 + i) * 8 + oct]);
                    }
                }
            }
            fence_acq();
            if (w < SEQ / WIN - 1) load_flags(tw + WIN);

            float hs[WIN];                          // window-buffered outputs

            #pragma unroll
            for (int s = 0; s < WIN; s++) {
                const int t = tw + s;
                float zn = zp[(size_t)(t + 1) * zstr];

                // recurrent dot, tree-shaped (h register-replicated)
                float s01 = fmaf(h[1], Whr[1], h[0] * Whr[0]);
                float s23 = fmaf(h[3], Whr[3], h[2] * Whr[2]);
                float s45 = fmaf(h[5], Whr[5], h[4] * Whr[4]);
                float s67 = fmaf(h[7], Whr[7], h[6] * Whr[6]);
                float z = zcur + ((s01 + s23) + (s45 + s67));

                float cv = __cosf(z) * cth;

                // exchange 1 (sync-free): share cos values within gate group
                sts_x(st1, cv);
                float4 va = lds128_x(rd1a);
                float4 vb = lds128_x(rd1b);

                float u1 = p1 ? va.y : 1.f, u2 = p2 ? va.z : 1.f, u3 = p3 ? va.w : 1.f;
                float u4 = p4 ? vb.x : 1.f, u5 = p5 ? vb.y : 1.f, u6 = p6 ? vb.z : 1.f;
                float u7 = p7 ? vb.w : 1.f;
                float pr = ((va.x * u1) * (u2 * u3)) * ((u4 * u5) * (u6 * u7));

                float th = tanh_approx(pr);
                float a  = fmaf(s2, th, s3);

                // exchange 2 (sync-free): gather (f,i,u,o) for my qubit
                sts_x(st2, a);
                float4 fiuo = lds128_x(rd2);

                c    = fmaf(fiuo.x, c, fiuo.y * fiuo.z);
                hnew = fiuo.w * tanh_approx(c);

                // exchange 3 (sync-free): broadcast h vector
                sts_x(st3, hnew);
                float4 ha = lds128_x(rd3a);
                float4 hb = lds128_x(rd3b);
                h[0] = ha.x; h[1] = ha.y; h[2] = ha.z; h[3] = ha.w;
                h[4] = hb.x; h[5] = hb.y; h[6] = hb.z; h[7] = hb.w;

                hs[s] = hnew;
                zcur  = zn;
            }

            // batched, off-critical-path stores (4x same-addr dup, same value)
            #pragma unroll
            for (int s = 0; s < WIN; s++)
                out[(size_t)(tw + s) * (BATCH * HDIM) + (size_t)b * HDIM + q] = hs[s];
        }

        hx_out[(size_t)b * HDIM + q] = hnew;
        cx_out[(size_t)b * HDIM + q] = c;
    }
}

extern "C" void kernel_launch(void* const* d_in, const int* in_sizes, int n_in,
                              void* d_out, int out_size) {
    const float* inputs = (const float*)d_in[0];
    const float* Wf = (const float*)d_in[1];  const float* bf = (const float*)d_in[2];
    const float* Wi = (const float*)d_in[3];  const float* bi = (const float*)d_in[4];
    const float* Wu = (const float*)d_in[5];  const float* bu = (const float*)d_in[6];
    const float* Wo = (const float*)d_in[7];  const float* bo = (const float*)d_in[8];
    const float* pf  = (const float*)d_in[9];
    const float* pi_ = (const float*)d_in[10];
    const float* pu  = (const float*)d_in[11];
    const float* po  = (const float*)d_in[12];
    float* out = (float*)d_out;

    init_flags<<<9, 256>>>();
    qlstm_fused<<<RECUR_BLOCKS + GEMM_BLOCKS, 256>>>(
        inputs, Wf, bf, Wi, bi, Wu, bu, Wo, bo, pf, pi_, pu, po, out);
}

// round 14
// speedup vs baseline: 1.4195x; 1.0395x over previous
#include <cuda_runtime.h>
#include <cstdint>

#define SEQ     256
#define BATCH   512
#define IN_DIM  256
#define HDIM    8
#define DIN     264          // IN_DIM + HDIM
#define NROWS   (SEQ * BATCH)

// Scratch: pre-activations, bias folded in.
// Layout: zx[(t*BATCH + b)*32 + (g*8 + q)]  (column = lane in both roles)
// Padded one t-row so the recur prefetch never reads OOB.
__device__ __align__(16) float g_zx[(size_t)(NROWS + BATCH) * 32];

// Ready flags: one per gemm tile (128 rows = quarter of one t).
// fidx = t*4 + qt, qt = b>>7.  [0,1024) real, [1024,1152) pad preset to 1.
#define NFLAG_REAL 1024
#define NFLAG_PAD  1152
__device__ unsigned g_flag[NFLAG_PAD];

typedef unsigned long long ull;

__device__ __forceinline__ void ffma2(ull &d, ull a, ull b) {
    asm("fma.rn.f32x2 %0, %1, %2, %0;" : "+l"(d) : "l"(a), "l"(b));
}
__device__ __forceinline__ float tanh_approx(float x) {
    float y; asm("tanh.approx.f32 %0, %1;" : "=f"(y) : "f"(x)); return y;
}
__device__ __forceinline__ void cpasync16(void* dst, const void* src) {
    unsigned ds = (unsigned)__cvta_generic_to_shared(dst);
    asm volatile("cp.async.cg.shared.global [%0], [%1], 16;" :: "r"(ds), "l"(src));
}
__device__ __forceinline__ void cp_commit() { asm volatile("cp.async.commit_group;"); }
template <int N> __device__ __forceinline__ void cp_wait() {
    asm volatile("cp.async.wait_group %0;" :: "n"(N));
}
__device__ __forceinline__ unsigned ld_acq(const unsigned* p) {
    unsigned v; asm volatile("ld.acquire.gpu.global.b32 %0, [%1];" : "=r"(v) : "l"(p)); return v;
}
__device__ __forceinline__ unsigned ld_rlx(const unsigned* p) {
    unsigned v; asm volatile("ld.relaxed.gpu.global.b32 %0, [%1];" : "=r"(v) : "l"(p)); return v;
}
__device__ __forceinline__ void st_rel(unsigned* p, unsigned v) {
    asm volatile("st.release.gpu.global.b32 [%0], %1;" :: "l"(p), "r"(v));
}
__device__ __forceinline__ void fence_acq() {
    asm volatile("fence.acq_rel.gpu;" ::: "memory");
}

// Sync-free warp-convergent smem exchange primitives (r13-proven): asm
// volatile keeps STS->LDS program order; a convergent warp issues per-warp
// in program order, so the LDS sees all lanes' STS data. NO WARPSYNC.
__device__ __forceinline__ void sts_x(unsigned a, float v) {
    asm volatile("st.volatile.shared.f32 [%0], %1;" :: "r"(a), "f"(v));
}
__device__ __forceinline__ float4 lds128_x(unsigned a) {
    float4 r;
    asm volatile("ld.volatile.shared.v4.f32 {%0,%1,%2,%3}, [%4];"
                 : "=f"(r.x), "=f"(r.y), "=f"(r.z), "=f"(r.w) : "r"(a));
    return r;
}

__global__ void init_flags() {
    int i = blockIdx.x * blockDim.x + threadIdx.x;
    if (i < NFLAG_PAD) g_flag[i] = (i < NFLAG_REAL) ? 0u : 1u;
}

// ---------------------------------------------------------------------------
// Fused kernel. Blocks 0..63: recur (8 warps = 8 batch elems each).
// Blocks 64..1087: gemm tiles of 128 rows (r3-proven shape), st.release flag.
// 64KB static smem -> 3 blocks/SM: a recur SM co-hosts only 2 gemm blocks.
// ---------------------------------------------------------------------------
#define GEMM_BLOCKS 1024
#define RECUR_BLOCKS 64
#define KCH    32
#define NCHUNK 8
#define WIN    16

union SmemU {
    struct { float w_s[32 * 256]; float xs[2][128 * 32]; } g;  // 32KB + 32KB
    float ex[8][80];    // per warp: cv[32], a[32], h[8], pad
};

__global__ void __launch_bounds__(256)
qlstm_fused(const float* __restrict__ x,
            const float* __restrict__ Wf, const float* __restrict__ bf,
            const float* __restrict__ Wi, const float* __restrict__ bi,
            const float* __restrict__ Wu, const float* __restrict__ bu,
            const float* __restrict__ Wo, const float* __restrict__ bo,
            const float* __restrict__ pf, const float* __restrict__ pi_,
            const float* __restrict__ pu, const float* __restrict__ po,
            float* __restrict__ out)
{
    __shared__ __align__(16) SmemU sm;

    const int tid  = threadIdx.x;
    const int lane = tid & 31;

    if (blockIdx.x >= RECUR_BLOCKS) {
        // ================= GEMM role: 128 rows = tile gb ===================
        const int gb   = blockIdx.x - RECUR_BLOCKS;
        const int warp = tid >> 5;
        const int row0  = gb * 128;
        const int wrow0 = warp * 16;

        float* w_s = sm.g.w_s;

        // Stage W x-part: 32 rows x 64 16B-slots = 2048, 8 per thread, swizzled.
        #pragma unroll
        for (int i = 0; i < 8; i++) {
            int idx = tid + 256 * i;
            int o = idx >> 6, s = idx & 63;
            int sw = (s & ~7) | ((s & 7) ^ (o & 7));
            int g = o >> 3, q = o & 7;
            const float* base = (g == 0 ? Wf : (g == 1 ? Wi : (g == 2 ? Wu : Wo)));
            cpasync16(&w_s[o * 256 + sw * 4], base + q * DIN + s * 4);
        }

        auto load_x = [&](int kc, int buf) {
            #pragma unroll
            for (int i = 0; i < 4; i++) {
                int idx = tid + 256 * i;          // 1024 slots: 128 rows x 8
                int r = idx >> 3, s = idx & 7;
                cpasync16(&sm.g.xs[buf][r * 32 + s * 4],
                          x + (size_t)(row0 + r) * IN_DIM + kc * KCH + s * 4);
            }
        };

        load_x(0, 0); cp_commit();                // group: {W, x0}

        ull acc[16];
        #pragma unroll
        for (int r = 0; r < 16; r++) acc[r] = 0ULL;

        #pragma unroll 1
        for (int kc = 0; kc < NCHUNK; kc++) {
            if (kc < NCHUNK - 1) { load_x(kc + 1, (kc + 1) & 1); cp_commit(); }
            if (kc < NCHUNK - 1) cp_wait<1>(); else cp_wait<0>();
            __syncthreads();

            ull wreg[16];
            #pragma unroll
            for (int j = 0; j < 8; j++) {
                int s  = kc * 8 + j;
                int sw = (s & ~7) | ((s & 7) ^ (lane & 7));
                ulonglong2 wv = *reinterpret_cast<const ulonglong2*>(&w_s[lane * 256 + sw * 4]);
                wreg[2 * j] = wv.x; wreg[2 * j + 1] = wv.y;
            }

            const float* xb = sm.g.xs[kc & 1];
            #pragma unroll
            for (int r = 0; r < 16; r++) {
                const ulonglong2* xp = reinterpret_cast<const ulonglong2*>(xb + (wrow0 + r) * 32);
                #pragma unroll
                for (int j = 0; j < 8; j++) {
                    ulonglong2 xv = xp[j];         // full-warp broadcast LDS.128
                    ffma2(acc[r], xv.x, wreg[2 * j]);
                    ffma2(acc[r], xv.y, wreg[2 * j + 1]);
                }
            }
            __syncthreads();
        }

        const int g = lane >> 3, q = lane & 7;
        const float bias = (g == 0 ? bf : (g == 1 ? bi : (g == 2 ? bu : bo)))[q];

        #pragma unroll
        for (int r = 0; r < 16; r++) {
            float2 p = *reinterpret_cast<float2*>(&acc[r]);
            g_zx[(size_t)(row0 + wrow0 + r) * 32 + lane] = p.x + p.y + bias;
        }

        __syncthreads();
        // tile gb covers rows [gb*128,(gb+1)*128): t = gb>>2, qt = gb&3
        // -> fidx = (gb>>2)*4 + (gb&3) = gb
        if (tid == 0) st_rel(&g_flag[gb], 1u);
    } else {
        // ================= RECUR role: 8 chains per block ==================
        const int wid = tid >> 5;
        const int b   = blockIdx.x * 8 + wid;
        const int qt  = blockIdx.x >> 4;           // == b>>7, uniform per block
        const int g = lane >> 3, q = lane & 7;

        // shared-address registers for the sync-free exchanges
        float* exw = &sm.ex[wid][0];
        const unsigned cvb = (unsigned)__cvta_generic_to_shared(exw);
        const unsigned ab  = cvb + 32 * 4;
        const unsigned hbm = cvb + 64 * 4;
        const unsigned st1 = cvb + lane * 4;
        const unsigned rd1a = cvb + g * 32, rd1b = rd1a + 16;
        const unsigned st2 = ab + (q * 4 + g) * 4;
        const unsigned rd2 = ab + q * 16;
        const unsigned st3 = hbm + q * 4;          // 4 lanes dup same value: ok
        const unsigned rd3a = hbm, rd3b = hbm + 16;

        const float* W = (g == 0 ? Wf : (g == 1 ? Wi : (g == 2 ? Wu : Wo))) + q * DIN + IN_DIM;
        const float* p = (g == 0 ? pf : (g == 1 ? pi_ : (g == 2 ? pu : po)));

        float Whr[8];
        #pragma unroll
        for (int j = 0; j < 8; j++) Whr[j] = W[j];

        // Prefix constant: CTHP_q = 0.5^{g!=2} * prod_{j<=q} cos(theta_j).
        // Lanes exchange RAW cos(z); the theta product and the sigmoid 0.5x
        // fold are applied once here, off the per-step chain.
        float cthp = (g == 2) ? 1.f : 0.5f;
        #pragma unroll
        for (int j = 0; j < 8; j++) if (j <= q) cthp *= __cosf(p[j]);
        const float s2 = (g == 2) ? 1.f : 0.5f;
        const float s3 = (g == 2) ? 0.f : 0.5f;

        const bool p1 = (q >= 1), p2 = (q >= 2), p3 = (q >= 3),
                   p4 = (q >= 4), p5 = (q >= 5), p6 = (q >= 6), p7 = (q >= 7);

        const float* zp = g_zx + (size_t)b * 32 + lane;
        const size_t zstr = (size_t)BATCH * 32;

        float* hx_out = out + (size_t)SEQ * BATCH * HDIM;
        float* cx_out = hx_out + (size_t)BATCH * HDIM;

        float h[8];
        #pragma unroll
        for (int j = 0; j < 8; j++) h[j] = 0.f;
        float c = 0.f, hnew = 0.f;

        // 16-step flag windows, loaded one window early (latency hidden).
        unsigned fv[WIN];
        auto load_flags = [&](int w16) {           // flags for t = w16+1..w16+16
            #pragma unroll
            for (int i = 0; i < WIN; i++)
                fv[i] = ld_rlx(&g_flag[(w16 + 1 + i) * 4 + qt]);
        };

        {   // t=0 tile (blocking acquire)
            unsigned r = ld_acq(&g_flag[qt]);
            while (r == 0) { __nanosleep(128); r = ld_acq(&g_flag[qt]); }
        }
        load_flags(0);
        float zcur = zp[0];

        #pragma unroll 1
        for (int w = 0; w < SEQ / WIN; w++) {
            const int tw = w * WIN;

            unsigned allv = fv[0];
            #pragma unroll
            for (int i = 1; i < WIN; i++) allv &= fv[i];
            if (allv == 0) {                        // warp-uniform branch
                #pragma unroll
                for (int i = 0; i < WIN; i++) {
                    while (fv[i] == 0) {
                        __nanosleep(128);
                        fv[i] = ld_rlx(&g_flag[(tw + 1 + i) * 4 + qt]);
                    }
                }
            }
            fence_acq();
            if (w < SEQ / WIN - 1) load_flags(tw + WIN);

            float hs[WIN];                          // window-buffered outputs

            #pragma unroll
            for (int s = 0; s < WIN; s++) {
                const int t = tw + s;
                float zn = zp[(size_t)(t + 1) * zstr];

                // recurrent dot, tree-shaped (h register-replicated)
                float s01 = fmaf(h[1], Whr[1], h[0] * Whr[0]);
                float s23 = fmaf(h[3], Whr[3], h[2] * Whr[2]);
                float s45 = fmaf(h[5], Whr[5], h[4] * Whr[4]);
                float s67 = fmaf(h[7], Whr[7], h[6] * Whr[6]);
                float z = zcur + ((s01 + s23) + (s45 + s67));

                // exchange 1 (sync-free): share RAW cos within gate group
                float cz = __cosf(z);
                sts_x(st1, cz);
                float4 va = lds128_x(rd1a);
                float4 vb = lds128_x(rd1b);

                float u1 = p1 ? va.y : 1.f, u2 = p2 ? va.z : 1.f, u3 = p3 ? va.w : 1.f;
                float u4 = p4 ? vb.x : 1.f, u5 = p5 ? vb.y : 1.f, u6 = p6 ? vb.z : 1.f;
                float u7 = p7 ? vb.w : 1.f;
                float pr = (((va.x * u1) * (u2 * u3)) * ((u4 * u5) * (u6 * u7))) * cthp;

                float th = tanh_approx(pr);
                float a  = fmaf(s2, th, s3);

                // exchange 2 (sync-free): gather (f,i,u,o) for my qubit
                sts_x(st2, a);
                float4 fiuo = lds128_x(rd2);

                c    = fmaf(fiuo.x, c, fiuo.y * fiuo.z);
                hnew = fiuo.w * tanh_approx(c);

                // exchange 3 (sync-free): broadcast h vector
                sts_x(st3, hnew);
                float4 ha = lds128_x(rd3a);
                float4 hb = lds128_x(rd3b);
                h[0] = ha.x; h[1] = ha.y; h[2] = ha.z; h[3] = ha.w;
                h[4] = hb.x; h[5] = hb.y; h[6] = hb.z; h[7] = hb.w;

                hs[s] = hnew;
                zcur  = zn;
            }

            // batched, off-critical-path stores (4x same-addr dup, same value)
            #pragma unroll
            for (int s = 0; s < WIN; s++)
                out[(size_t)(tw + s) * (BATCH * HDIM) + (size_t)b * HDIM + q] = hs[s];
        }

        hx_out[(size_t)b * HDIM + q] = hnew;
        cx_out[(size_t)b * HDIM + q] = c;
    }
}

extern "C" void kernel_launch(void* const* d_in, const int* in_sizes, int n_in,
                              void* d_out, int out_size) {
    const float* inputs = (const float*)d_in[0];
    const float* Wf = (const float*)d_in[1];  const float* bf = (const float*)d_in[2];
    const float* Wi = (const float*)d_in[3];  const float* bi = (const float*)d_in[4];
    const float* Wu = (const float*)d_in[5];  const float* bu = (const float*)d_in[6];
    const float* Wo = (const float*)d_in[7];  const float* bo = (const float*)d_in[8];
    const float* pf  = (const float*)d_in[9];
    const float* pi_ = (const float*)d_in[10];
    const float* pu  = (const float*)d_in[11];
    const float* po  = (const float*)d_in[12];
    float* out = (float*)d_out;

    init_flags<<<5, 256>>>();
    qlstm_fused<<<RECUR_BLOCKS + GEMM_BLOCKS, 256>>>(
        inputs, Wf, bf, Wi, bi, Wu, bu, Wo, bo, pf, pi_, pu, po, out);
}

// round 15
// speedup vs baseline: 1.5506x; 1.0923x over previous
#include <cuda_runtime.h>
#include <cstdint>

#define SEQ     256
#define BATCH   512
#define IN_DIM  256
#define HDIM    8
#define DIN     264          // IN_DIM + HDIM
#define NROWS   (SEQ * BATCH)

// Scratch: pre-activations, bias folded in.
// Layout: zx[(t*BATCH + b)*32 + (g*8 + q)]  (column = lane in both roles)
// Padded one t-row so the recur prefetch never reads OOB.
__device__ __align__(16) float g_zx[(size_t)(NROWS + BATCH) * 32];

// Ready flags: one per gemm tile (128 rows = quarter of one t).
// fidx = t*4 + qt, qt = b>>7.  [0,1024) real, [1024,1152) pad preset to 1.
#define NFLAG_REAL 1024
#define NFLAG_PAD  1152
__device__ unsigned g_flag[NFLAG_PAD];

typedef unsigned long long ull;

__device__ __forceinline__ void ffma2(ull &d, ull a, ull b) {
    asm("fma.rn.f32x2 %0, %1, %2, %0;" : "+l"(d) : "l"(a), "l"(b));
}
__device__ __forceinline__ float tanh_approx(float x) {
    float y; asm("tanh.approx.f32 %0, %1;" : "=f"(y) : "f"(x)); return y;
}
__device__ __forceinline__ void cpasync16(void* dst, const void* src) {
    unsigned ds = (unsigned)__cvta_generic_to_shared(dst);
    asm volatile("cp.async.cg.shared.global [%0], [%1], 16;" :: "r"(ds), "l"(src));
}
__device__ __forceinline__ void cp_commit() { asm volatile("cp.async.commit_group;"); }
template <int N> __device__ __forceinline__ void cp_wait() {
    asm volatile("cp.async.wait_group %0;" :: "n"(N));
}
__device__ __forceinline__ unsigned ld_acq(const unsigned* p) {
    unsigned v; asm volatile("ld.acquire.gpu.global.b32 %0, [%1];" : "=r"(v) : "l"(p)); return v;
}
__device__ __forceinline__ unsigned ld_rlx(const unsigned* p) {
    unsigned v; asm volatile("ld.relaxed.gpu.global.b32 %0, [%1];" : "=r"(v) : "l"(p)); return v;
}
__device__ __forceinline__ void st_rel(unsigned* p, unsigned v) {
    asm volatile("st.release.gpu.global.b32 [%0], %1;" :: "l"(p), "r"(v));
}
__device__ __forceinline__ void fence_acq() {
    asm volatile("fence.acq_rel.gpu;" ::: "memory");
}

// Sync-free warp-convergent smem exchange primitives (r13-proven).
__device__ __forceinline__ void sts_x(unsigned a, float v) {
    asm volatile("st.volatile.shared.f32 [%0], %1;" :: "r"(a), "f"(v));
}
__device__ __forceinline__ float4 lds128_x(unsigned a) {
    float4 r;
    asm volatile("ld.volatile.shared.v4.f32 {%0,%1,%2,%3}, [%4];"
                 : "=f"(r.x), "=f"(r.y), "=f"(r.z), "=f"(r.w) : "r"(a));
    return r;
}

__global__ void init_flags() {
    int i = blockIdx.x * blockDim.x + threadIdx.x;
    if (i < NFLAG_PAD) g_flag[i] = (i < NFLAG_REAL) ? 0u : 1u;
}

// ---------------------------------------------------------------------------
// Fused kernel. Blocks 0..63: recur (8 warps = 8 batch elems, r14-identical).
// Blocks 64..1087: gemm tiles of 128 rows with a 2-D lane tile
// (4 rows x 4 outputs): 64 LDS + 256 FFMA2 per warp-chunk -> FMA-bound.
// ---------------------------------------------------------------------------
#define GEMM_BLOCKS 1024
#define RECUR_BLOCKS 64
#define KCH    32
#define NCHUNK 8
#define WIN    16

union SmemU {
    struct { float w_s[32 * 256]; float xs[2][128 * 32]; } g;  // 32KB + 32KB
    float ex[8][80];    // per warp: cv[32], a[32], h[8], pad
};

__global__ void __launch_bounds__(256)
qlstm_fused(const float* __restrict__ x,
            const float* __restrict__ Wf, const float* __restrict__ bf,
            const float* __restrict__ Wi, const float* __restrict__ bi,
            const float* __restrict__ Wu, const float* __restrict__ bu,
            const float* __restrict__ Wo, const float* __restrict__ bo,
            const float* __restrict__ pf, const float* __restrict__ pi_,
            const float* __restrict__ pu, const float* __restrict__ po,
            float* __restrict__ out)
{
    __shared__ __align__(16) SmemU sm;

    const int tid  = threadIdx.x;
    const int lane = tid & 31;

    if (blockIdx.x >= RECUR_BLOCKS) {
        // ================= GEMM role: 128 rows = tile gb ===================
        const int gb   = blockIdx.x - RECUR_BLOCKS;
        const int warp = tid >> 5;
        const int ri   = lane >> 3;           // 0..3: row group within warp
        const int oi   = lane & 7;            // 0..7: output qubit
        const int row0  = gb * 128;
        const int wrow0 = warp * 16;

        float* w_s = sm.g.w_s;

        // Stage W x-part: 32 rows x 64 16B-slots, swizzled by (o&7).
        #pragma unroll
        for (int i = 0; i < 8; i++) {
            int idx = tid + 256 * i;
            int o = idx >> 6, s = idx & 63;
            int sw = (s & ~7) | ((s & 7) ^ (o & 7));
            int g = o >> 3, q = o & 7;
            const float* base = (g == 0 ? Wf : (g == 1 ? Wi : (g == 2 ? Wu : Wo)));
            cpasync16(&w_s[o * 256 + sw * 4], base + q * DIN + s * 4);
        }

        // x loader: rows swizzled by (r>>2)&3 so the 4 concurrently-read
        // rows (fixed rr, varying ri) hit 4 distinct slot groups.
        auto load_x = [&](int kc, int buf) {
            #pragma unroll
            for (int i = 0; i < 4; i++) {
                int idx = tid + 256 * i;          // 1024 slots: 128 rows x 8
                int r = idx >> 3, s = idx & 7;
                int sw2 = s ^ ((r >> 2) & 3);
                cpasync16(&sm.g.xs[buf][r * 32 + sw2 * 4],
                          x + (size_t)(row0 + r) * IN_DIM + kc * KCH + s * 4);
            }
        };

        load_x(0, 0); cp_commit();                // group: {W, x0}

        // acc[rr][m]: row wrow0+4*ri+rr, output oi+8m; ull = (k-even,k-odd)
        ull acc[4][4];
        #pragma unroll
        for (int rr = 0; rr < 4; rr++)
            #pragma unroll
            for (int m = 0; m < 4; m++) acc[rr][m] = 0ULL;

        #pragma unroll 1
        for (int kc = 0; kc < NCHUNK; kc++) {
            if (kc < NCHUNK - 1) { load_x(kc + 1, (kc + 1) & 1); cp_commit(); }
            if (kc < NCHUNK - 1) cp_wait<1>(); else cp_wait<0>();
            __syncthreads();

            const float* xb = sm.g.xs[kc & 1];

            #pragma unroll
            for (int j = 0; j < 8; j++) {
                // W: 4 outputs (oi + 8m), slot s = kc*8+j, swizzle by oi
                const int s  = kc * 8 + j;
                const int sw = (s & ~7) | ((s & 7) ^ oi);
                ulonglong2 wv[4];
                #pragma unroll
                for (int m = 0; m < 4; m++)
                    wv[m] = *reinterpret_cast<const ulonglong2*>(
                        &w_s[(oi + 8 * m) * 256 + sw * 4]);

                // x: 4 rows (wrow0 + 4*ri + rr), swizzled slot
                ulonglong2 xv[4];
                #pragma unroll
                for (int rr = 0; rr < 4; rr++) {
                    int r = wrow0 + 4 * ri + rr;
                    int sw2 = j ^ ((r >> 2) & 3);
                    xv[rr] = *reinterpret_cast<const ulonglong2*>(
                        &xb[r * 32 + sw2 * 4]);
                }

                #pragma unroll
                for (int rr = 0; rr < 4; rr++)
                    #pragma unroll
                    for (int m = 0; m < 4; m++) {
                        ffma2(acc[rr][m], xv[rr].x, wv[m].x);
                        ffma2(acc[rr][m], xv[rr].y, wv[m].y);
                    }
            }
            __syncthreads();
        }

        // Epilogue: bias per output (o = m*8 + oi -> gate m, qubit oi)
        float bias[4] = { bf[oi], bi[oi], bu[oi], bo[oi] };

        #pragma unroll
        for (int rr = 0; rr < 4; rr++) {
            int row = row0 + wrow0 + 4 * ri + rr;
            #pragma unroll
            for (int m = 0; m < 4; m++) {
                float2 p = *reinterpret_cast<float2*>(&acc[rr][m]);
                g_zx[(size_t)row * 32 + m * 8 + oi] = p.x + p.y + bias[m];
            }
        }

        __syncthreads();
        if (tid == 0) st_rel(&g_flag[gb], 1u);     // fidx == gb == t*4 + qt
    } else {
        // ============ RECUR role: 8 chains per block (r14-identical) =======
        const int wid = tid >> 5;
        const int b   = blockIdx.x * 8 + wid;
        const int qt  = blockIdx.x >> 4;           // == b>>7, uniform per block
        const int g = lane >> 3, q = lane & 7;

        float* exw = &sm.ex[wid][0];
        const unsigned cvb = (unsigned)__cvta_generic_to_shared(exw);
        const unsigned ab  = cvb + 32 * 4;
        const unsigned hbm = cvb + 64 * 4;
        const unsigned st1 = cvb + lane * 4;
        const unsigned rd1a = cvb + g * 32, rd1b = rd1a + 16;
        const unsigned st2 = ab + (q * 4 + g) * 4;
        const unsigned rd2 = ab + q * 16;
        const unsigned st3 = hbm + q * 4;
        const unsigned rd3a = hbm, rd3b = hbm + 16;

        const float* W = (g == 0 ? Wf : (g == 1 ? Wi : (g == 2 ? Wu : Wo))) + q * DIN + IN_DIM;
        const float* p = (g == 0 ? pf : (g == 1 ? pi_ : (g == 2 ? pu : po)));

        float Whr[8];
        #pragma unroll
        for (int j = 0; j < 8; j++) Whr[j] = W[j];

        float cthp = (g == 2) ? 1.f : 0.5f;
        #pragma unroll
        for (int j = 0; j < 8; j++) if (j <= q) cthp *= __cosf(p[j]);
        const float s2 = (g == 2) ? 1.f : 0.5f;
        const float s3 = (g == 2) ? 0.f : 0.5f;

        const bool p1 = (q >= 1), p2 = (q >= 2), p3 = (q >= 3),
                   p4 = (q >= 4), p5 = (q >= 5), p6 = (q >= 6), p7 = (q >= 7);

        const float* zp = g_zx + (size_t)b * 32 + lane;
        const size_t zstr = (size_t)BATCH * 32;

        float* hx_out = out + (size_t)SEQ * BATCH * HDIM;
        float* cx_out = hx_out + (size_t)BATCH * HDIM;

        float h[8];
        #pragma unroll
        for (int j = 0; j < 8; j++) h[j] = 0.f;
        float c = 0.f, hnew = 0.f;

        unsigned fv[WIN];
        auto load_flags = [&](int w16) {
            #pragma unroll
            for (int i = 0; i < WIN; i++)
                fv[i] = ld_rlx(&g_flag[(w16 + 1 + i) * 4 + qt]);
        };

        {
            unsigned r = ld_acq(&g_flag[qt]);
            while (r == 0) { __nanosleep(128); r = ld_acq(&g_flag[qt]); }
        }
        load_flags(0);
        float zcur = zp[0];

        #pragma unroll 1
        for (int w = 0; w < SEQ / WIN; w++) {
            const int tw = w * WIN;

            unsigned allv = fv[0];
            #pragma unroll
            for (int i = 1; i < WIN; i++) allv &= fv[i];
            if (allv == 0) {
                #pragma unroll
                for (int i = 0; i < WIN; i++) {
                    while (fv[i] == 0) {
                        __nanosleep(128);
                        fv[i] = ld_rlx(&g_flag[(tw + 1 + i) * 4 + qt]);
                    }
                }
            }
            fence_acq();
            if (w < SEQ / WIN - 1) load_flags(tw + WIN);

            float hs[WIN];

            #pragma unroll
            for (int s = 0; s < WIN; s++) {
                const int t = tw + s;
                float zn = zp[(size_t)(t + 1) * zstr];

                float s01 = fmaf(h[1], Whr[1], h[0] * Whr[0]);
                float s23 = fmaf(h[3], Whr[3], h[2] * Whr[2]);
                float s45 = fmaf(h[5], Whr[5], h[4] * Whr[4]);
                float s67 = fmaf(h[7], Whr[7], h[6] * Whr[6]);
                float z = zcur + ((s01 + s23) + (s45 + s67));

                float cz = __cosf(z);
                sts_x(st1, cz);
                float4 va = lds128_x(rd1a);
                float4 vb = lds128_x(rd1b);

                float u1 = p1 ? va.y : 1.f, u2 = p2 ? va.z : 1.f, u3 = p3 ? va.w : 1.f;
                float u4 = p4 ? vb.x : 1.f, u5 = p5 ? vb.y : 1.f, u6 = p6 ? vb.z : 1.f;
                float u7 = p7 ? vb.w : 1.f;
                float pr = (((va.x * u1) * (u2 * u3)) * ((u4 * u5) * (u6 * u7))) * cthp;

                float th = tanh_approx(pr);
                float a  = fmaf(s2, th, s3);

                sts_x(st2, a);
                float4 fiuo = lds128_x(rd2);

                c    = fmaf(fiuo.x, c, fiuo.y * fiuo.z);
                hnew = fiuo.w * tanh_approx(c);

                sts_x(st3, hnew);
                float4 ha = lds128_x(rd3a);
                float4 hb = lds128_x(rd3b);
                h[0] = ha.x; h[1] = ha.y; h[2] = ha.z; h[3] = ha.w;
                h[4] = hb.x; h[5] = hb.y; h[6] = hb.z; h[7] = hb.w;

                hs[s] = hnew;
                zcur  = zn;
            }

            #pragma unroll
            for (int s = 0; s < WIN; s++)
                out[(size_t)(tw + s) * (BATCH * HDIM) + (size_t)b * HDIM + q] = hs[s];
        }

        hx_out[(size_t)b * HDIM + q] = hnew;
        cx_out[(size_t)b * HDIM + q] = c;
    }
}

extern "C" void kernel_launch(void* const* d_in, const int* in_sizes, int n_in,
                              void* d_out, int out_size) {
    const float* inputs = (const float*)d_in[0];
    const float* Wf = (const float*)d_in[1];  const float* bf = (const float*)d_in[2];
    const float* Wi = (const float*)d_in[3];  const float* bi = (const float*)d_in[4];
    const float* Wu = (const float*)d_in[5];  const float* bu = (const float*)d_in[6];
    const float* Wo = (const float*)d_in[7];  const float* bo = (const float*)d_in[8];
    const float* pf  = (const float*)d_in[9];
    const float* pi_ = (const float*)d_in[10];
    const float* pu  = (const float*)d_in[11];
    const float* po  = (const float*)d_in[12];
    float* out = (float*)d_out;

    init_flags<<<5, 256>>>();
    qlstm_fused<<<RECUR_BLOCKS + GEMM_BLOCKS, 256>>>(
        inputs, Wf, bf, Wi, bi, Wu, bu, Wo, bo, pf, pi_, pu, po, out);
}